// round 10
// baseline (speedup 1.0000x reference)
#include <cuda_runtime.h>
#include <cstdint>

// BiologicalWorkingMemory: B x (S=8 slots, D=64 dims) fused update.
// R10: 4 lanes per batch, 8 batches per warp, 128 threads/block -> 32
// batches/block. The 56-pair chain is lockstep-replicated per lane, so its
// ~900 warp-instructions now serve 8 batches instead of 4. No SMEM: the
// dense apply m_out = L*m0 reloads m0 from global (L2-resident, DRAM has
// headroom). Chain maintains Gram G + composed operator L (2 columns/lane);
// decay folded into L init; refresh/deact/write-blend scales folded into L.

static __device__ __forceinline__ float gsum4(float v) {
    v += __shfl_xor_sync(0xffffffffu, v, 1);
    v += __shfl_xor_sync(0xffffffffu, v, 2);
    return v;
}

static __device__ __forceinline__ float dot4(float4 a, float4 b) {
    return (a.x * b.x + a.y * b.y) + (a.z * b.z + a.w * b.w);
}

// symmetric index for a<=b into 36-entry triangle
#define GIDX(a, b) ((a) * 8 - (a) * ((a) + 1) / 2 + (b))
#define GSYM(a, b) ((a) <= (b) ? GIDX(a, b) : GIDX(b, a))

__global__ __launch_bounds__(128, 4) void wm_kernel(
    const float* __restrict__ mem,        // (B,8,64)
    const float* __restrict__ act_in,     // (B,8)
    const float* __restrict__ gate_in,    // (B,8)
    const float* __restrict__ thr_in,     // (B,8)
    const float* __restrict__ refresh_in, // (B,8)
    const float* __restrict__ intf,       // (B,8,8)
    const float* __restrict__ maint_in,   // (B,8)
    const float* __restrict__ x_in,       // (B,64)
    const float* __restrict__ gsig_in,    // (B,8)
    const float* __restrict__ rsig_in,    // (B,8)
    const void* __restrict__ dt_ptr,
    float* __restrict__ out,
    int B)
{
    const unsigned FULL = 0xffffffffu;
    const int lane = threadIdx.x & 31;
    const int warp = blockIdx.x * (blockDim.x >> 5) + (threadIdx.x >> 5);
    const int grp  = lane >> 2;   // batch within warp (0..7)
    const int r2   = lane & 3;    // lane within batch group
    const int b    = warp * 8 + grp;
    const bool valid = (b < B);
    const int bb = valid ? b : (B - 1);
    const int sA = r2;            // low slot owned by this lane
    const int sB2 = r2 + 4;       // high slot owned by this lane
    const int nsh = grp * 4;      // ballot nibble shift

    // dt may arrive as int32 or float32 scalar; decode by bit-pattern heuristic.
    float dtf;
    {
        int di = *(const int*)dt_ptr;
        dtf = (di > -16777216 && di < 16777216) ? (float)di : __int_as_float(di);
    }

    // ---- per-slot scalars: lane owns slots r2 and r2+4 ----
    const size_t s8 = (size_t)bb * 8;
    const float act0A = act_in[s8 + sA];
    const float act0B = act_in[s8 + sB2];

    // interference rows r2 and r2+4 (8 floats each)
    const float4* ip = (const float4*)(intf + (size_t)bb * 64);
    const float4 IA0 = ip[r2 * 2], IA1 = ip[r2 * 2 + 1];
    const float4 IB0 = ip[(r2 + 4) * 2], IB1 = ip[(r2 + 4) * 2 + 1];
    const float Ilo[8] = {IA0.x, IA0.y, IA0.z, IA0.w, IA1.x, IA1.y, IA1.z, IA1.w};
    const float Ihi[8] = {IB0.x, IB0.y, IB0.z, IB0.w, IB1.x, IB1.y, IB1.z, IB1.w};

    // ---- Gram matrix: 4 passes, lane owns float4 indices {4p + r2} ----
    const float4* mp4 = (const float4*)(mem + (size_t)bb * 512);
    float G[36];
#pragma unroll
    for (int t = 0; t < 36; t++) G[t] = 0.0f;
#pragma unroll
    for (int p = 0; p < 4; p++) {
        float4 m4[8];
#pragma unroll
        for (int s = 0; s < 8; s++) m4[s] = mp4[s * 16 + p * 4 + r2];
#pragma unroll
        for (int a = 0; a < 8; a++)
#pragma unroll
            for (int c = a; c < 8; c++)
                G[GIDX(a, c)] += dot4(m4[a], m4[c]);
    }
#pragma unroll
    for (int t = 0; t < 36; t++) G[t] = gsum4(G[t]);

    // ---- prefetch remaining operands (latency hidden under the chain) ----
    const float gateA = gate_in[s8 + sA],   gateB = gate_in[s8 + sB2];
    const float thrA  = thr_in[s8 + sA],    thrB  = thr_in[s8 + sB2];
    const float rstrA = refresh_in[s8 + sA], rstrB = refresh_in[s8 + sB2];
    const float maintA= maint_in[s8 + sA],  maintB= maint_in[s8 + sB2];
    const float gsigA = gsig_in[s8 + sA],   gsigB = gsig_in[s8 + sB2];
    const float rsigA = rsig_in[s8 + sA],   rsigB = rsig_in[s8 + sB2];
    const float4* xp4 = (const float4*)(x_in + (size_t)bb * 64);
    float4 xv[4];
#pragma unroll
    for (int p = 0; p < 4; p++) xv[p] = xp4[p * 4 + r2];

    // ---- activity decay + 8-bit masks from nibble ballots ----
    const float adecA = act0A * 0.9f, adecB = act0B * 0.9f;
    unsigned balLo = __ballot_sync(FULL, adecA > 0.1f);
    unsigned balHi = __ballot_sync(FULL, adecB > 0.1f);
    const unsigned actMask = ((balLo >> nsh) & 0xFu) | (((balHi >> nsh) & 0xFu) << 4);
    balLo = __ballot_sync(FULL, act0A < 0.2f);
    balHi = __ballot_sync(FULL, act0B < 0.2f);
    const unsigned avMask = ((balLo >> nsh) & 0xFu) | (((balHi >> nsh) & 0xFu) << 4);

    // ---- target slot: argmin with jnp tie-break (lowest index) ----
    const float INF = __int_as_float(0x7f800000);
    float kA = avMask ? ((act0A < 0.2f) ? act0A : INF) : act0A;
    float kB = avMask ? ((act0B < 0.2f) ? act0B : INF) : act0B;
    float key; int idx;
    if (kB < kA) { key = kB; idx = sB2; } else { key = kA; idx = sA; }  // tie -> lower idx
#pragma unroll
    for (int off = 1; off < 4; off <<= 1) {
        float ov = __shfl_xor_sync(FULL, key, off);
        int   oi = __shfl_xor_sync(FULL, idx, off);
        if (ov < key || (ov == key && oi < idx)) { key = ov; idx = oi; }
    }
    const int ts = idx;  // uniform within group

    // ---- sequential interference chain on G; L columns r2 and r2+4 ----
    float LA[8], LB[8];
#pragma unroll
    for (int i = 0; i < 8; i++) {
        LA[i] = (i == sA)  ? 0.95f : 0.0f;
        LB[i] = (i == sB2) ? 0.95f : 0.0f;
    }

#pragma unroll
    for (int i = 0; i < 8; i++) {
        float Kc[8];
        const bool acti = (actMask >> i) & 1u;
#pragma unroll
        for (int j = 0; j < 8; j++) {
            if (j == i) { Kc[j] = 0.0f; continue; }
            const float Iv = __shfl_sync(FULL, (i < 4) ? Ilo[j] : Ihi[j], i & 3, 4);
            const bool cond = acti && ((actMask >> j) & 1u);
            Kc[j] = cond ? 0.1f * Iv : 0.0f;
        }
#pragma unroll
        for (int j = 0; j < 8; j++) {
            if (i == j) continue;
            const float Gij = G[GSYM(i, j)];
            const float Gjj = G[GIDX(j, j)];
            const float c = Kc[j] * Gij * rsqrtf(G[GIDX(i, i)] * Gjj);
            const float GiiNew = fmaf(c, fmaf(c, Gjj, -2.0f * Gij), G[GIDX(i, i)]);
#pragma unroll
            for (int k = 0; k < 8; k++) {
                if (k == i) continue;
                G[GSYM(i, k)] = fmaf(-c, G[GSYM(j, k)], G[GSYM(i, k)]);
            }
            G[GIDX(i, i)] = GiiNew;
            LA[i] = fmaf(-c, LA[j], LA[i]);
            LB[i] = fmaf(-c, LB[j], LB[i]);
        }
    }

    // ---- gating / write ----
    const float gvA = 0.7f * gateA + 0.3f * __saturatef(gsigA);
    const float gvB = 0.7f * gateB + 0.3f * __saturatef(gsigB);
    const float gs = __shfl_sync(FULL, (ts >= 4) ? gvB : gvA, ts & 3, 4);
    const float th = __shfl_sync(FULL, (ts >= 4) ? thrB : thrA, ts & 3, 4);
    const bool write = gs > th;

    float in2loc = 0.0f;
#pragma unroll
    for (int p = 0; p < 4; p++) in2loc += dot4(xv[p], xv[p]);
    const float inorm = sqrtf(gsum4(in2loc));

    float aA = (write && ts == sA)  ? inorm : adecA;
    float aB = (write && ts == sB2) ? inorm : adecB;

    // ---- refresh ----
    const float ruA = __saturatef(rsigA);
    const float ruB = __saturatef(rsigB);
    const float rsA = (ruA > 0.1f) ? rstrA * ruA : 0.0f;
    const float rsB = (ruB > 0.1f) ? rstrB * ruB : 0.0f;
    aA += rsA;
    aB += rsB;

    // ---- maintenance ----
    const float mcA = (aA > 0.1f)
        ? fmaf(fmaf(0.5f, aA, -maintA), 0.1f * dtf, maintA) : maintA * 0.95f;
    const float mcB = (aB > 0.1f)
        ? fmaf(fmaf(0.5f, aB, -maintB), 0.1f * dtf, maintB) : maintB * 0.95f;

    // ---- capacity limiting: rank active slots ascending (stable ties) ----
    float ab[8];
#pragma unroll
    for (int s = 0; s < 4; s++) {
        ab[s]     = __shfl_sync(FULL, aA, s, 4);
        ab[s + 4] = __shfl_sync(FULL, aB, s, 4);
    }
    balLo = __ballot_sync(FULL, aA > 0.1f);
    balHi = __ballot_sync(FULL, aB > 0.1f);
    const unsigned activeMask = ((balLo >> nsh) & 0xFu) | (((balHi >> nsh) & 0xFu) << 4);
    const int ndeact = __popc(activeMask) - 4;
    int rankA = 0, rankB = 0;
#pragma unroll
    for (int s = 0; s < 8; s++) {
        const bool sa = (activeMask >> s) & 1u;
        if (sa && (ab[s] < aA || (ab[s] == aA && s < sA)))  rankA++;
        if (sa && (ab[s] < aB || (ab[s] == aB && s < sB2))) rankB++;
    }
    const bool deA = ((activeMask >> sA) & 1u)  && (rankA < ndeact);
    const bool deB = ((activeMask >> sB2) & 1u) && (rankB < ndeact);
    const float afinA = deA ? aA * 0.5f : aA;
    const float afinB = deB ? aB * 0.5f : aB;
    balLo = __ballot_sync(FULL, deA);
    balHi = __ballot_sync(FULL, deB);
    const unsigned deMask = ((balLo >> nsh) & 0xFu) | (((balHi >> nsh) & 0xFu) << 4);

    // per-slot refresh scales broadcast (constant-indexed only)
    float rsb[8];
#pragma unroll
    for (int s = 0; s < 4; s++) {
        rsb[s]     = __shfl_sync(FULL, rsA, s, 4);
        rsb[s + 4] = __shfl_sync(FULL, rsB, s, 4);
    }

    // ---- fold all row scales into L ----
    const float wgt = write ? gs * 0.3f : 0.0f;
#pragma unroll
    for (int i = 0; i < 8; i++) {
        float rowS = (1.0f + rsb[i]) * (((deMask >> i) & 1u) ? 0.7f : 1.0f);
        if (i == ts) rowS *= (1.0f - wgt);
        LA[i] *= rowS;
        LB[i] *= rowS;
    }
    // input-blend coefficient for the target row (avoid dynamic array index)
    const float rs_ts = __shfl_sync(FULL, (ts >= 4) ? rsB : rsA, ts & 3, 4);
    const float wS = wgt * (1.0f + rs_ts) * (((deMask >> ts) & 1u) ? 0.7f : 1.0f);

    // ---- dense apply m_out = L * m0, reloading m0 from global (L2-hot) ----
    float4* op4 = (float4*)(out + (size_t)b * 512);
#pragma unroll
    for (int p = 0; p < 4; p++) {
        float4 ck[8];
#pragma unroll
        for (int k = 0; k < 8; k++) ck[k] = mp4[k * 16 + p * 4 + r2];
        float4 acc[8];
#pragma unroll
        for (int i = 0; i < 8; i++) acc[i] = make_float4(0.f, 0.f, 0.f, 0.f);
#pragma unroll
        for (int k = 0; k < 8; k++) {
#pragma unroll
            for (int i = 0; i < 8; i++) {
                const float Lik = __shfl_sync(FULL, (k < 4) ? LA[i] : LB[i], k & 3, 4);
                acc[i].x = fmaf(Lik, ck[k].x, acc[i].x);
                acc[i].y = fmaf(Lik, ck[k].y, acc[i].y);
                acc[i].z = fmaf(Lik, ck[k].z, acc[i].z);
                acc[i].w = fmaf(Lik, ck[k].w, acc[i].w);
            }
        }
        if (valid) {
#pragma unroll
            for (int i = 0; i < 8; i++) {
                float4 o = acc[i];
                if (i == ts) {
                    o.x = fmaf(wS, xv[p].x, o.x);
                    o.y = fmaf(wS, xv[p].y, o.y);
                    o.z = fmaf(wS, xv[p].z, o.z);
                    o.w = fmaf(wS, xv[p].w, o.w);
                }
                op4[i * 16 + p * 4 + r2] = o;
            }
        }
    }

    // ---- per-batch reductions + scalar outputs ----
    const float tot  = gsum4(afinA + afinB);
    const float msum = gsum4(mcA + mcB);
    balLo = __ballot_sync(FULL, afinA > 0.1f);
    balHi = __ballot_sync(FULL, afinB > 0.1f);
    const int mload = __popc(((balLo >> nsh) & 0xFu) | (((balHi >> nsh) & 0xFu) << 4));

    const size_t OA  = (size_t)B * 512;      // m size
    const size_t SB8 = (size_t)B * 8;
    if (valid) {
        const size_t ob = (size_t)b * 8;
        out[OA + ob + sA]            = afinA;  // a
        out[OA + ob + sB2]           = afinB;
        out[OA + SB8 + ob + sA]      = gvA;    // g
        out[OA + SB8 + ob + sB2]     = gvB;
        out[OA + 2 * SB8 + ob + sA]  = mcA;    // mc
        out[OA + 2 * SB8 + ob + sB2] = mcB;
        if (r2 == 0) {
            out[OA + 3 * SB8 + (size_t)b]                 = (float)mload;
            out[OA + 3 * SB8 + (size_t)B + (size_t)b]     = tot;
            out[OA + 3 * SB8 + 2 * (size_t)B + (size_t)b] = msum * 0.125f;
        }
    }
}

extern "C" void kernel_launch(void* const* d_in, const int* in_sizes, int n_in,
                              void* d_out, int out_size)
{
    const int B = in_sizes[0] / 512;   // B*S*D / (8*64)
    const int threads = 128;           // 4 warps * 8 batches = 32 batches/block
    const int batchesPerBlock = 32;
    const int grid = (B + batchesPerBlock - 1) / batchesPerBlock;
    wm_kernel<<<grid, threads>>>(
        (const float*)d_in[0], (const float*)d_in[1], (const float*)d_in[2],
        (const float*)d_in[3], (const float*)d_in[4], (const float*)d_in[5],
        (const float*)d_in[6], (const float*)d_in[7], (const float*)d_in[8],
        (const float*)d_in[9], (const void*)d_in[10],
        (float*)d_out, B);
}

// round 13
// speedup vs baseline: 4.2469x; 4.2469x over previous
#include <cuda_runtime.h>
#include <cstdint>

// BiologicalWorkingMemory: B x (S=8 slots, D=64 dims) fused update.
// 8 lanes per batch, 4 batches per warp, 128 threads/block -> 16 batches/block.
//
// R13 = R6 structure (per-warp chain, m parked in barrier-free SMEM, composed
// operator L, dense apply) + fma.rn.f32x2 (FFMA2) packed apply. redux.f32 was
// rejected by ptxas on sm_100 (R12), so all reductions use the shfl butterfly.

static __device__ __forceinline__ float gsum8(float v) {
    v += __shfl_xor_sync(0xffffffffu, v, 1);
    v += __shfl_xor_sync(0xffffffffu, v, 2);
    v += __shfl_xor_sync(0xffffffffu, v, 4);
    return v;
}

static __device__ __forceinline__ unsigned long long pk2(float x, float y) {
    unsigned long long r;
    asm("mov.b64 %0, {%1, %2};" : "=l"(r) : "f"(x), "f"(y));
    return r;
}

static __device__ __forceinline__ unsigned long long ffma2(
    unsigned long long a, unsigned long long b, unsigned long long c) {
    unsigned long long d;
    asm("fma.rn.f32x2 %0, %1, %2, %3;" : "=l"(d) : "l"(a), "l"(b), "l"(c));
    return d;
}

static __device__ __forceinline__ float dot4(float4 a, float4 b) {
    return (a.x * b.x + a.y * b.y) + (a.z * b.z + a.w * b.w);
}

// symmetric index for a<=b into 36-entry triangle
#define GIDX(a, b) ((a) * 8 - (a) * ((a) + 1) / 2 + (b))
#define GSYM(a, b) ((a) <= (b) ? GIDX(a, b) : GIDX(b, a))

__global__ __launch_bounds__(128, 4) void wm_kernel(
    const float* __restrict__ mem,        // (B,8,64)
    const float* __restrict__ act_in,     // (B,8)
    const float* __restrict__ gate_in,    // (B,8)
    const float* __restrict__ thr_in,     // (B,8)
    const float* __restrict__ refresh_in, // (B,8)
    const float* __restrict__ intf,       // (B,8,8)
    const float* __restrict__ maint_in,   // (B,8)
    const float* __restrict__ x_in,       // (B,64)
    const float* __restrict__ gsig_in,    // (B,8)
    const float* __restrict__ rsig_in,    // (B,8)
    const void* __restrict__ dt_ptr,
    float* __restrict__ out,
    int B)
{
    // 16 batches * (8 slots * 17 float4 + pad); slot stride 17 f4 avoids bank conflicts
    __shared__ float4 sm[16 * 137];

    const unsigned FULL = 0xffffffffu;
    const int lane = threadIdx.x & 31;
    const int warp = blockIdx.x * (blockDim.x >> 5) + (threadIdx.x >> 5);
    const int grp  = lane >> 3;   // batch within warp
    const int r    = lane & 7;    // slot rank / chunk rank / L column
    const int b    = warp * 4 + grp;
    const bool valid = (b < B);
    const int bb = valid ? b : (B - 1);
    const int wb = ((threadIdx.x >> 5) << 2) | grp;   // batch within block
    const int base4 = wb * 137;

    // dt may arrive as int32 or float32 scalar; decode by bit-pattern heuristic.
    float dtf;
    {
        int di = *(const int*)dt_ptr;
        dtf = (di > -16777216 && di < 16777216) ? (float)di : __int_as_float(di);
    }

    // ---- early per-slot scalar: activity (needed pre-chain) ----
    const size_t sb = (size_t)bb * 8 + r;
    const float act0 = act_in[sb];

    // interference row r (8 floats)
    const float4* ip = (const float4*)(intf + (size_t)bb * 64 + (size_t)r * 8);
    const float4 I0 = ip[0], I1 = ip[1];
    const float Irow[8] = {I0.x, I0.y, I0.z, I0.w, I1.x, I1.y, I1.z, I1.w};

    // ---- pass A: first halves (lane r owns words [r*4, r*4+4) of each slot) ----
    const float4* mp4 = (const float4*)(mem + (size_t)bb * 512);
    float4 m4[8];
    float G[36];
#pragma unroll
    for (int s = 0; s < 8; s++) m4[s] = mp4[s * 16 + r];
#pragma unroll
    for (int s = 0; s < 8; s++) sm[base4 + s * 17 + r] = m4[s];
#pragma unroll
    for (int a = 0; a < 8; a++)
#pragma unroll
        for (int c = a; c < 8; c++)
            G[GIDX(a, c)] = dot4(m4[a], m4[c]);

    // ---- pass B: second halves (words [32 + r*4, 32 + r*4 + 4)) ----
#pragma unroll
    for (int s = 0; s < 8; s++) m4[s] = mp4[s * 16 + 8 + r];
#pragma unroll
    for (int s = 0; s < 8; s++) sm[base4 + s * 17 + 8 + r] = m4[s];
#pragma unroll
    for (int a = 0; a < 8; a++)
#pragma unroll
        for (int c = a; c < 8; c++)
            G[GIDX(a, c)] += dot4(m4[a], m4[c]);

    // reduce all 36 Gram entries across the 8 lanes (pipelined shuffles)
#pragma unroll
    for (int t = 0; t < 36; t++) G[t] = gsum8(G[t]);

    // ---- prefetch epilogue operands (latency hidden under the chain) ----
    const float gate = gate_in[sb];
    const float thr  = thr_in[sb];
    const float rstr = refresh_in[sb];
    const float maint= maint_in[sb];
    const float gsig = gsig_in[sb];
    const float rsig = rsig_in[sb];
    const float4* xp4 = (const float4*)(x_in + (size_t)bb * 64);
    const float4 xA = xp4[r];
    const float4 xB = xp4[8 + r];

    // ---- activity decay + masks ----
    const float adec = act0 * 0.9f;
    const unsigned actBall = __ballot_sync(FULL, adec > 0.1f);
    const unsigned actMask = (actBall >> (grp * 8)) & 0xffu;
    const unsigned avBall = __ballot_sync(FULL, act0 < 0.2f);
    const unsigned avMask = (avBall >> (grp * 8)) & 0xffu;

    // ---- target slot: argmin with jnp tie-break (lowest index) ----
    const float INF = __int_as_float(0x7f800000);
    float key = avMask ? ((act0 < 0.2f) ? act0 : INF) : act0;
    int idx = r;
#pragma unroll
    for (int off = 1; off < 8; off <<= 1) {
        float ov = __shfl_xor_sync(FULL, key, off);
        int   oi = __shfl_xor_sync(FULL, idx, off);
        if (ov < key || (ov == key && oi < idx)) { key = ov; idx = oi; }
    }
    const int ts = idx;  // uniform within group

    // ---- sequential interference chain on G; L tracks the composed operator.
    //      Gram is on UN-decayed m (sim is scale-invariant); decay folded into L.
    float Lcol[8];
#pragma unroll
    for (int i = 0; i < 8; i++) Lcol[i] = (i == r) ? 0.95f : 0.0f;

#pragma unroll
    for (int i = 0; i < 8; i++) {
        float Kc[8];
#pragma unroll
        for (int j = 0; j < 8; j++) {
            if (j == i) { Kc[j] = 0.0f; continue; }
            const float Iv = __shfl_sync(FULL, Irow[j], i, 8);
            const bool cond = ((actMask >> i) & 1u) && ((actMask >> j) & 1u);
            Kc[j] = cond ? 0.1f * Iv : 0.0f;
        }
#pragma unroll
        for (int j = 0; j < 8; j++) {
            if (i == j) continue;
            const float Gij = G[GSYM(i, j)];
            const float Gjj = G[GIDX(j, j)];
            const float c = Kc[j] * Gij * rsqrtf(G[GIDX(i, i)] * Gjj);
            const float GiiNew = fmaf(c, fmaf(c, Gjj, -2.0f * Gij), G[GIDX(i, i)]);
#pragma unroll
            for (int k = 0; k < 8; k++) {
                if (k == i) continue;
                G[GSYM(i, k)] = fmaf(-c, G[GSYM(j, k)], G[GSYM(i, k)]);
            }
            G[GIDX(i, i)] = GiiNew;
            Lcol[i] = fmaf(-c, Lcol[j], Lcol[i]);   // operator row-op, 1 FMA/lane
        }
    }

    // ---- gating / write ----
    const float gv = 0.7f * gate + 0.3f * __saturatef(gsig);
    const float gs = __shfl_sync(FULL, gv, ts, 8);
    const float th = __shfl_sync(FULL, thr, ts, 8);
    const bool write = gs > th;

    const float in2 = gsum8(dot4(xA, xA) + dot4(xB, xB));
    const float inorm = sqrtf(in2);

    float a = adec;
    if (write && r == ts) a = inorm;

    // ---- refresh ----
    const float ru = __saturatef(rsig);
    const float rs = (ru > 0.1f) ? rstr * ru : 0.0f;
    a += rs;

    // ---- maintenance ----
    const float mc = (a > 0.1f)
        ? fmaf(fmaf(0.5f, a, -maint), 0.1f * dtf, maint)
        : maint * 0.95f;

    // ---- capacity limiting: rank active slots ascending (stable ties) ----
    float ab[8];
#pragma unroll
    for (int s = 0; s < 8; s++) ab[s] = __shfl_sync(FULL, a, s, 8);
    const unsigned activeBall = __ballot_sync(FULL, a > 0.1f);
    const unsigned activeMask = (activeBall >> (grp * 8)) & 0xffu;
    const int ndeact = __popc(activeMask) - 4;
    int rank = 0;
#pragma unroll
    for (int s = 0; s < 8; s++) {
        const bool sa = (activeMask >> s) & 1u;
        if (sa && (ab[s] < a || (ab[s] == a && s < r))) rank++;
    }
    const bool active_r = (activeMask >> r) & 1u;
    const bool deact = active_r && (rank < ndeact);
    const float afin = deact ? a * 0.5f : a;
    const unsigned deBall = __ballot_sync(FULL, deact);
    const unsigned deMask = (deBall >> (grp * 8)) & 0xffu;

    // per-slot refresh scales broadcast
    float rsb[8];
#pragma unroll
    for (int s = 0; s < 8; s++) rsb[s] = __shfl_sync(FULL, rs, s, 8);

    // ---- fold all row scales into L ----
    const float wgt = write ? gs * 0.3f : 0.0f;
#pragma unroll
    for (int i = 0; i < 8; i++) {
        float rowS = (1.0f + rsb[i]) * (((deMask >> i) & 1u) ? 0.7f : 1.0f);
        if (i == ts) rowS *= (1.0f - wgt);
        Lcol[i] *= rowS;
    }
    // input-blend coefficient for the target row (post-scale)
    const float wS = wgt * (1.0f + rsb[ts]) * (((deMask >> ts) & 1u) ? 0.7f : 1.0f);

    // packed operands for the apply
    const unsigned long long wS2 = pk2(wS, wS);
    const unsigned long long xpk[4] = {
        pk2(xA.x, xA.y), pk2(xA.z, xA.w), pk2(xB.x, xB.y), pk2(xB.z, xB.w)
    };

    // ---- dense apply m_out = L * m0 from SMEM, packed f32x2 FMAs ----
    const ulonglong2* smp = (const ulonglong2*)sm;
    ulonglong2* opp = (ulonglong2*)(out + (size_t)b * 512);
#pragma unroll
    for (int p = 0; p < 2; p++) {
        unsigned long long aA0[4], aA1[4], aB0[4], aB1[4];
#pragma unroll
        for (int q = 0; q < 4; q++) { aA0[q] = aA1[q] = aB0[q] = aB1[q] = 0ULL; }
#pragma unroll
        for (int k = 0; k < 8; k++) {
            const ulonglong2 c0 = smp[base4 + k * 17 + r];
            const ulonglong2 c1 = smp[base4 + k * 17 + 8 + r];
#pragma unroll
            for (int q = 0; q < 4; q++) {
                const float Lik = __shfl_sync(FULL, Lcol[p * 4 + q], k, 8);
                const unsigned long long L2 = pk2(Lik, Lik);
                aA0[q] = ffma2(L2, c0.x, aA0[q]);
                aA1[q] = ffma2(L2, c0.y, aA1[q]);
                aB0[q] = ffma2(L2, c1.x, aB0[q]);
                aB1[q] = ffma2(L2, c1.y, aB1[q]);
            }
        }
        if (valid) {
#pragma unroll
            for (int q = 0; q < 4; q++) {
                const int i = p * 4 + q;
                unsigned long long oA0 = aA0[q], oA1 = aA1[q];
                unsigned long long oB0 = aB0[q], oB1 = aB1[q];
                if (i == ts) {
                    oA0 = ffma2(wS2, xpk[0], oA0);
                    oA1 = ffma2(wS2, xpk[1], oA1);
                    oB0 = ffma2(wS2, xpk[2], oB0);
                    oB1 = ffma2(wS2, xpk[3], oB1);
                }
                opp[i * 16 + r]     = make_ulonglong2(oA0, oA1);
                opp[i * 16 + 8 + r] = make_ulonglong2(oB0, oB1);
            }
        }
    }

    // ---- per-batch reductions + scalar outputs ----
    const float tot  = gsum8(afin);
    const float msum = gsum8(mc);
    const unsigned loadBall = __ballot_sync(FULL, afin > 0.1f);
    const int mload = __popc((loadBall >> (grp * 8)) & 0xffu);

    const size_t OA  = (size_t)B * 512;      // m size
    const size_t SB8 = (size_t)B * 8;
    if (valid) {
        out[OA + (size_t)b * 8 + r]           = afin;  // a
        out[OA + SB8 + (size_t)b * 8 + r]     = gv;    // g
        out[OA + 2 * SB8 + (size_t)b * 8 + r] = mc;    // mc
        if (r == 0) {
            out[OA + 3 * SB8 + (size_t)b]                 = (float)mload;
            out[OA + 3 * SB8 + (size_t)B + (size_t)b]     = tot;
            out[OA + 3 * SB8 + 2 * (size_t)B + (size_t)b] = msum * 0.125f;
        }
    }
}

extern "C" void kernel_launch(void* const* d_in, const int* in_sizes, int n_in,
                              void* d_out, int out_size)
{
    const int B = in_sizes[0] / 512;   // B*S*D / (8*64)
    const int threads = 128;           // 4 warps * 4 batches = 16 batches/block
    const int batchesPerBlock = 16;
    const int grid = (B + batchesPerBlock - 1) / batchesPerBlock;
    wm_kernel<<<grid, threads>>>(
        (const float*)d_in[0], (const float*)d_in[1], (const float*)d_in[2],
        (const float*)d_in[3], (const float*)d_in[4], (const float*)d_in[5],
        (const float*)d_in[6], (const float*)d_in[7], (const float*)d_in[8],
        (const float*)d_in[9], (const void*)d_in[10],
        (float*)d_out, B);
}